// round 5
// baseline (speedup 1.0000x reference)
#include <cuda_runtime.h>
#include <cstdint>

// AdaPool2D, R3: MUFU-bound at R2 (56 MUFU/thread * rt8 = 448 cyc/thread/SMSP
// == measured 80us). Fixes:
//  - all 6 reciprocals per channel -> bit-trick + 2 Newton iters (FMA pipe)
//  - all FMA-pipe math packed f32x2 (2 channels per instruction, PTX-only)
//  - exp via packed mul-by-log2e + scalar MUFU.EX2 (register-pair aliasing, free)
// New model: FMA 272 cyc < DRAM ~410 cyc -> DRAM-bound ~74-78us.

#define BDIM 32
#define WDIM 224
#define HDIM 224
#define WO 112
#define HO 112
#define C4 16  // 64 channels / 4 per thread

typedef unsigned long long u64v;

__device__ __forceinline__ u64v pk(float lo, float hi) {
    u64v r; asm("mov.b64 %0, {%1, %2};" : "=l"(r) : "f"(lo), "f"(hi)); return r;
}
__device__ __forceinline__ u64v fma2(u64v a, u64v b, u64v c) {
    u64v r; asm("fma.rn.f32x2 %0, %1, %2, %3;" : "=l"(r) : "l"(a), "l"(b), "l"(c)); return r;
}
__device__ __forceinline__ u64v mul2(u64v a, u64v b) {
    u64v r; asm("mul.rn.f32x2 %0, %1, %2;" : "=l"(r) : "l"(a), "l"(b)); return r;
}
__device__ __forceinline__ u64v add2(u64v a, u64v b) {
    u64v r; asm("add.rn.f32x2 %0, %1, %2;" : "=l"(r) : "l"(a), "l"(b)); return r;
}

// exp(x) for both packed halves: packed mul by log2(e) done by caller; here EX2.
__device__ __forceinline__ u64v ex2_2(u64v v) {
    float lo, hi, rlo, rhi;
    asm("mov.b64 {%0, %1}, %2;" : "=f"(lo), "=f"(hi) : "l"(v));
    asm("ex2.approx.f32 %0, %1;" : "=f"(rlo) : "f"(lo));
    asm("ex2.approx.f32 %0, %1;" : "=f"(rhi) : "f"(hi));
    return pk(rlo, rhi);
}

// Packed reciprocal: bit-trick initial guess (~9% err) + 2 Newton iters (~6e-5).
// Valid for positive normal denominators (all ours are sums of squares / exps).
#define TWO2 0x4000000040000000ull
__device__ __forceinline__ u64v rcp2n(u64v d) {
    uint32_t lo = (uint32_t)d, hi = (uint32_t)(d >> 32);
    uint32_t glo = 0x7EF127EAu - lo;
    uint32_t ghi = 0x7EF127EAu - hi;
    u64v r = ((u64v)ghi << 32) | (u64v)glo;
    u64v nd = d ^ 0x8000000080000000ull;  // -d (sign flip both halves)
    r = mul2(r, fma2(nd, r, TWO2));       // r *= (2 - d*r)
    r = mul2(r, fma2(nd, r, TWO2));
    return r;
}

__device__ __forceinline__ u64v ada2(u64v a, u64v b, u64v c, u64v d,
                                     u64v mk2, u64v omk2, u64v log2e2, u64v quarter2) {
    // --- exponential-maximum (softmax) pooling, no shift (inputs ~N(0,1)) ---
    u64v ea = ex2_2(mul2(a, log2e2));
    u64v eb = ex2_2(mul2(b, log2e2));
    u64v ec = ex2_2(mul2(c, log2e2));
    u64v ed = ex2_2(mul2(d, log2e2));
    u64v den = add2(add2(ea, eb), add2(ec, ed));
    u64v num = fma2(a, ea, fma2(b, eb, fma2(c, ec, mul2(d, ed))));
    u64v em  = mul2(num, rcp2n(den));

    // --- eDSCW: dsc = 2*avg*x / (avg^2 + x^2), softmax-weighted (dsc in [-1,1]) ---
    u64v avg = mul2(add2(add2(a, b), add2(c, d)), quarter2);
    u64v av2 = mul2(avg, avg);
    u64v ta  = add2(avg, avg);
    u64v da = mul2(mul2(ta, a), rcp2n(fma2(a, a, av2)));
    u64v db = mul2(mul2(ta, b), rcp2n(fma2(b, b, av2)));
    u64v dc = mul2(mul2(ta, c), rcp2n(fma2(c, c, av2)));
    u64v dd = mul2(mul2(ta, d), rcp2n(fma2(d, d, av2)));
    u64v fa = ex2_2(mul2(da, log2e2));
    u64v fb = ex2_2(mul2(db, log2e2));
    u64v fc = ex2_2(mul2(dc, log2e2));
    u64v fd = ex2_2(mul2(dd, log2e2));
    u64v den2 = add2(add2(fa, fb), add2(fc, fd));
    u64v num2 = fma2(a, fa, fma2(b, fb, fma2(c, fc, mul2(d, fd))));
    u64v dscp = mul2(num2, rcp2n(den2));

    return fma2(em, mk2, mul2(dscp, omk2));
}

__global__ void __launch_bounds__(256)
adapool2d_kernel(const ulonglong2* __restrict__ in,
                 const float* __restrict__ mask,
                 ulonglong2* __restrict__ out) {
    // x covers (ho, c4): 112*16 = 1792 threads = 7 blocks of 256 exactly.
    int i  = blockIdx.x * blockDim.x + threadIdx.x;
    int c4 = i & (C4 - 1);
    int ho = i >> 4;
    int wo = blockIdx.y;
    int b  = blockIdx.z;

    float mk  = __ldg(mask);
    u64v mk2      = pk(mk, mk);
    u64v omk2     = pk(1.0f - mk, 1.0f - mk);
    u64v log2e2   = pk(1.4426950408889634f, 1.4426950408889634f);
    u64v quarter2 = pk(0.25f, 0.25f);

    int w0 = 2 * wo;
    int h0 = 2 * ho;

    const ulonglong2* r0 = in + ((size_t)(b * WDIM + w0) * HDIM + h0) * C4 + c4;
    const ulonglong2* r1 = r0 + (size_t)HDIM * C4;  // next input row (w0+1)

    // 2x2 window, 4 channels per thread (two packed f32x2 pairs): MLP=4 x 16B
    ulonglong2 p00 = r0[0];
    ulonglong2 p01 = r0[C4];
    ulonglong2 p10 = r1[0];
    ulonglong2 p11 = r1[C4];

    ulonglong2 o;
    o.x = ada2(p00.x, p01.x, p10.x, p11.x, mk2, omk2, log2e2, quarter2);
    o.y = ada2(p00.y, p01.y, p10.y, p11.y, mk2, omk2, log2e2, quarter2);

    out[((size_t)(b * WO + wo) * HO + ho) * C4 + c4] = o;
}

extern "C" void kernel_launch(void* const* d_in, const int* in_sizes, int n_in,
                              void* d_out, int out_size) {
    const ulonglong2* in   = (const ulonglong2*)d_in[0];
    const float*      mask = (const float*)d_in[1];
    ulonglong2*       out  = (ulonglong2*)d_out;

    dim3 block(256);
    dim3 grid(HO * C4 / 256, WO, BDIM);  // (7, 112, 32)
    adapool2d_kernel<<<grid, block>>>(in, mask, out);
}